// round 7
// baseline (speedup 1.0000x reference)
#include <cuda_runtime.h>
#include <cstdint>

// PARAFAC / CP reconstruction: out[a,b,c] = sum_k f0[k,a] * f1[k,b] * f2[k,c]
// A = B = C = 512, RANK = 16, fp32. 536 MB output.
//
// Round-7: OCCUPANCY experiment. Rounds 2-5 all pinned at 96-100us with no pipe
// saturated (fma 66, DRAM 58, L1 64, issue 50) at only ~20 warps/SM -> latency bound.
//   - c-PAIR threads (256/block): f2 residency drops 64->32 regs, total ~64 regs
//     -> launch_bounds(256,4) = 32 warps/SM (occ ~50%, 2.2x more than before)
//   - BCHUNK=128: halves block count & per-block prologue; g tile 8 KB in shared
//   - arithmetic: k-paired f32x2 (zero splat movs), same as round 3 -> same rel_err
//   - accepted cost: L1 rises to ~3 wf/128B (more warps re-reading g) -- it had headroom

#define A_DIM 512
#define B_DIM 512
#define C_DIM 512
#define RANK  16
#define BCHUNK 128
#define NTHREADS 256   // 256 c-lanes x 2 c each = 512 c

typedef unsigned long long ull;

__device__ __forceinline__ ull pack2(float lo, float hi) {
    ull r;
    asm("mov.b64 %0, {%1,%2};" : "=l"(r) : "r"(__float_as_uint(lo)), "r"(__float_as_uint(hi)));
    return r;
}

__global__ __launch_bounds__(NTHREADS, 4)
void parafac_kernel(const float* __restrict__ f0,
                    const float* __restrict__ f1,
                    const float* __restrict__ f2,
                    float* __restrict__ out)
{
    // g k-major & contiguous: gsh[j][k] = f0[k][a]*f1[k][b0+j]  (8 KB)
    __shared__ __align__(16) float gsh[BCHUNK][RANK];

    const int a  = blockIdx.y;
    const int b0 = blockIdx.x * BCHUNK;
    const int t  = threadIdx.x;
    const int c0 = t * 2;   // thread's fixed c-pair

    // ---- f2 transposed pack (once per block): f2p[p][c] = (f2[2p][c0+c], f2[2p+1][c0+c]) ----
    // 16 packed regs (32 registers) -- half the c-quad version's footprint.
    ull f2p[RANK / 2][2];
#pragma unroll
    for (int p = 0; p < RANK / 2; p++) {
        float2 e = *reinterpret_cast<const float2*>(f2 + (2 * p + 0) * C_DIM + c0);
        float2 o = *reinterpret_cast<const float2*>(f2 + (2 * p + 1) * C_DIM + c0);
        f2p[p][0] = pack2(e.x, o.x);
        f2p[p][1] = pack2(e.y, o.y);
    }

    // ---- precompute g: 128*16 = 2048 entries, 256 threads -> 8 each ----
#pragma unroll
    for (int i = 0; i < (BCHUNK * RANK) / NTHREADS; i++) {
        int idx = t + i * NTHREADS;
        int j = idx >> 4;     // b offset within chunk
        int k = idx & 15;     // rank index
        gsh[j][k] = f0[k * A_DIM + a] * f1[k * B_DIM + b0 + j];
    }
    __syncthreads();

    float* orow = out + (size_t)a * (B_DIM * C_DIM) + (size_t)b0 * C_DIM + c0;

#pragma unroll 2
    for (int j = 0; j < BCHUNK; j++) {
        // 4x LDS.128 (broadcast): 8 pre-packed (g_even, g_odd) pairs
        const ulonglong2* gj = reinterpret_cast<const ulonglong2*>(gsh[j]);
        ulonglong2 u0 = gj[0], u1 = gj[1], u2 = gj[2], u3 = gj[3];

        // 2 independent f32x2 accumulator chains (one per c); lanes = (even-k, odd-k) sums
        ull acc0 = 0ull, acc1 = 0ull;
#define STEP(gpair, p)                                                                   \
        asm("fma.rn.f32x2 %0, %1, %2, %0;" : "+l"(acc0) : "l"(f2p[p][0]), "l"(gpair));   \
        asm("fma.rn.f32x2 %0, %1, %2, %0;" : "+l"(acc1) : "l"(f2p[p][1]), "l"(gpair));
        STEP(u0.x, 0) STEP(u0.y, 1) STEP(u1.x, 2) STEP(u1.y, 3)
        STEP(u2.x, 4) STEP(u2.y, 5) STEP(u3.x, 6) STEP(u3.y, 7)
#undef STEP

        // horizontal add (even-sum + odd-sum) per c
        float2 h0 = *reinterpret_cast<float2*>(&acc0);
        float2 h1 = *reinterpret_cast<float2*>(&acc1);
        float r0 = h0.x + h0.y;
        float r1 = h1.x + h1.y;

        // streaming STG.64; warp covers 256B contiguous (fully coalesced)
        asm volatile("st.global.cs.v2.f32 [%0], {%1,%2};"
                     :: "l"(orow + (size_t)j * C_DIM), "f"(r0), "f"(r1)
                     : "memory");
    }
}

extern "C" void kernel_launch(void* const* d_in, const int* in_sizes, int n_in,
                              void* d_out, int out_size)
{
    const float* f0 = (const float*)d_in[0];
    const float* f1 = (const float*)d_in[1];
    const float* f2 = (const float*)d_in[2];
    float* out = (float*)d_out;

    dim3 grid(B_DIM / BCHUNK, A_DIM);   // (4, 512) = 2048 blocks
    dim3 block(NTHREADS);
    parafac_kernel<<<grid, block>>>(f0, f1, f2, out);
}